// round 16
// baseline (speedup 1.0000x reference)
#include <cuda_runtime.h>
#include <cstdint>
#include <math.h>

#define NB 16
#define NS 2048
#define NH 1024
#define NH4 (NH / 4)
#define NCOEF 7          // C0, C1, S1, C2, S2, C3, S3
#define NPART 37         // 16*37 = 592 = 148*4 CTAs (balanced wave)
#define MAXSEG 56
#define ROWS 16          // rows per block in fuse_ln
#define BATCH 4          // rows per TMA batch / barrier
#define NBATCH (ROWS / BATCH)  // 4
#define PIPE 3           // smem buffers (2 batches in flight)
#define GBYTES (BATCH * NH * 4)   // 16384 bytes per batch
#define LN_EPS 1e-12f

// twiddles: per s, {cos1,sin1,cos2,sin2,cos3,sin3,0,0}
__device__ __align__(16) float g_tw[NS][8];
__device__ float g_partial[NB][NPART][NCOEF][NH];
__device__ float g_coeff[NB][NCOEF][NH];

__device__ __forceinline__ float4 f4zero() { return make_float4(0.f, 0.f, 0.f, 0.f); }

// ---- TMA bulk 1D (global->shared::cta) + mbarrier helpers -----------------
__device__ __forceinline__ void mbar_init1(unsigned int mbar) {
    asm volatile("mbarrier.init.shared.b64 [%0], 1;" :: "r"(mbar) : "memory");
}
__device__ __forceinline__ void mbar_expect_tx(unsigned int mbar, unsigned int bytes) {
    asm volatile("mbarrier.arrive.expect_tx.shared.b64 _, [%0], %1;"
                 :: "r"(mbar), "r"(bytes) : "memory");
}
__device__ __forceinline__ void tma_bulk_1d(unsigned int sdst, const void* gsrc,
                                            unsigned int bytes, unsigned int mbar) {
    asm volatile("cp.async.bulk.shared::cta.global.mbarrier::complete_tx::bytes "
                 "[%0], [%1], %2, [%3];"
                 :: "r"(sdst), "l"(gsrc), "r"(bytes), "r"(mbar) : "memory");
}
__device__ __forceinline__ void mbar_wait(unsigned int mbar, unsigned int parity) {
    unsigned int done;
    asm volatile(
        "{\n\t.reg .pred p;\n\t"
        "mbarrier.try_wait.parity.acquire.cta.shared::cta.b64 p, [%1], %2;\n\t"
        "selp.b32 %0, 1, 0, p;\n\t}"
        : "=r"(done) : "r"(mbar), "r"(parity) : "memory");
    if (!done) {
        asm volatile(
            "{\n\t.reg .pred P1;\n\t"
            "WAIT_LOOP_%=:\n\t"
            "mbarrier.try_wait.parity.acquire.cta.shared::cta.b64 P1, [%0], %1, 0x989680;\n\t"
            "@P1 bra.uni WAIT_DONE_%=;\n\t"
            "bra.uni WAIT_LOOP_%=;\n\t"
            "WAIT_DONE_%=:\n\t}"
            :: "r"(mbar), "r"(parity) : "memory");
    }
}
// un-hoistable float4 load (keeps gamma/beta register lifetime to the epilogue)
__device__ __forceinline__ float4 ldg_f4_nohoist(const float4* p) {
    float4 v;
    asm volatile("ld.global.nc.v4.f32 {%0,%1,%2,%3}, [%4];"
                 : "=f"(v.x), "=f"(v.y), "=f"(v.z), "=f"(v.w) : "l"(p));
    return v;
}

// ---------------------------------------------------------------------------
// Kernel A: partial DFT sums; b==0 CTAs also publish the twiddle table.
// 592 CTAs = 148*4, perfectly balanced wave.
// ---------------------------------------------------------------------------
__global__ void __launch_bounds__(256) coeff_partial_kernel(const float* __restrict__ x) {
    const int cta = blockIdx.x;
    const int b   = cta / NPART;
    const int j   = cta % NPART;
    const int s_start = (j * NS) / NPART;
    const int s_end   = ((j + 1) * NS) / NPART;
    const int len     = s_end - s_start;          // 55 or 56
    const int tid     = threadIdx.x;

    __shared__ float4 tw4[MAXSEG][2];
    if (tid < len) {
        const int s = s_start + tid;
        float cv1, sv1, cv2, sv2, cv3, sv3;
        sincospif((float)s       * (1.0f / 1024.0f), &sv1, &cv1);
        sincospif((float)(2 * s) * (1.0f / 1024.0f), &sv2, &cv2);
        sincospif((float)(3 * s) * (1.0f / 1024.0f), &sv3, &cv3);
        tw4[tid][0] = make_float4(cv1, sv1, cv2, sv2);
        tw4[tid][1] = make_float4(cv3, sv3, 0.f, 0.f);
        if (b == 0) {   // publish twiddle table for fuse_ln
            *(float4*)&g_tw[s][0] = tw4[tid][0];
            *(float4*)&g_tw[s][4] = tw4[tid][1];
        }
    }
    __syncthreads();

    float4 a0 = f4zero(), a1 = f4zero(), b1 = f4zero(),
           a2 = f4zero(), b2 = f4zero(), a3 = f4zero(), b3 = f4zero();

    const float4* __restrict__ xp =
        (const float4*)(x + ((size_t)b * NS + s_start) * NH) + tid;

#pragma unroll 8
    for (int t = 0; t < len; t++) {
        float4 v = __ldcs(&xp[(size_t)t * NH4]);
        float4 t0 = tw4[t][0];
        float4 t1 = tw4[t][1];
        float c1 = t0.x, s1 = t0.y, c2 = t0.z, s2 = t0.w;
        float c3 = t1.x, s3 = t1.y;
        a0.x += v.x; a0.y += v.y; a0.z += v.z; a0.w += v.w;
        a1.x = fmaf(v.x, c1, a1.x); a1.y = fmaf(v.y, c1, a1.y);
        a1.z = fmaf(v.z, c1, a1.z); a1.w = fmaf(v.w, c1, a1.w);
        b1.x = fmaf(v.x, s1, b1.x); b1.y = fmaf(v.y, s1, b1.y);
        b1.z = fmaf(v.z, s1, b1.z); b1.w = fmaf(v.w, s1, b1.w);
        a2.x = fmaf(v.x, c2, a2.x); a2.y = fmaf(v.y, c2, a2.y);
        a2.z = fmaf(v.z, c2, a2.z); a2.w = fmaf(v.w, c2, a2.w);
        b2.x = fmaf(v.x, s2, b2.x); b2.y = fmaf(v.y, s2, b2.y);
        b2.z = fmaf(v.z, s2, b2.z); b2.w = fmaf(v.w, s2, b2.w);
        a3.x = fmaf(v.x, c3, a3.x); a3.y = fmaf(v.y, c3, a3.y);
        a3.z = fmaf(v.z, c3, a3.z); a3.w = fmaf(v.w, c3, a3.w);
        b3.x = fmaf(v.x, s3, b3.x); b3.y = fmaf(v.y, s3, b3.y);
        b3.z = fmaf(v.z, s3, b3.z); b3.w = fmaf(v.w, s3, b3.w);
    }

    ((float4*)g_partial[b][j][0])[tid] = a0;
    ((float4*)g_partial[b][j][1])[tid] = a1;
    ((float4*)g_partial[b][j][2])[tid] = b1;
    ((float4*)g_partial[b][j][3])[tid] = a2;
    ((float4*)g_partial[b][j][4])[tid] = b2;
    ((float4*)g_partial[b][j][5])[tid] = a3;
    ((float4*)g_partial[b][j][6])[tid] = b3;
}

// ---------------------------------------------------------------------------
// Kernel B: reduce NPART partials (deterministic) and pre-scale.
// ---------------------------------------------------------------------------
__global__ void coeff_reduce_kernel(const float* __restrict__ sqrt_beta) {
    const int i = blockIdx.x * blockDim.x + threadIdx.x;
    const int INNER4 = NCOEF * NH4;
    const int N4 = NB * INNER4;
    if (i >= N4) return;

    const int b  = i / INNER4;
    const int r  = i % INNER4;
    const int k  = r / NH4;
    const int h4 = r % NH4;

    const float4* p4 = (const float4*)&g_partial[b][0][0][0];
    float4 s = f4zero();
#pragma unroll 8
    for (int j = 0; j < NPART; j++) {
        float4 v = p4[(size_t)j * INNER4 + r];
        s.x += v.x; s.y += v.y; s.z += v.z; s.w += v.w;
    }

    const float4 sb = ((const float4*)sqrt_beta)[h4];
    const float base = (k == 0 ? 1.0f : 2.0f) / (float)NS;
    s.x *= (1.0f - sb.x * sb.x) * base;
    s.y *= (1.0f - sb.y * sb.y) * base;
    s.z *= (1.0f - sb.z * sb.z) * base;
    s.w *= (1.0f - sb.w * sb.w) * base;

    ((float4*)&g_coeff[b][k][0])[h4] = s;
}

// ---------------------------------------------------------------------------
// Kernel C: fused recombine + LayerNorm. gamma/beta loaded (un-hoistable) in
// the epilogue of each batch -> ~48KB smem, <=64 regs, TRUE 4 CTAs/SM.
// ---------------------------------------------------------------------------
__global__ void __launch_bounds__(256, 4) fuse_ln_kernel(
    const float* __restrict__ x,
    const float* __restrict__ sqrt_beta,
    const float* __restrict__ gamma,
    const float* __restrict__ beta,
    float* __restrict__ out)
{
    __shared__ float4 sx[PIPE][BATCH][NH4];
    __shared__ float2 sred[2][BATCH][8];
    __shared__ __align__(8) unsigned long long mbar[PIPE];

    const int base = blockIdx.x * ROWS;      // first row (b*NS + s)
    const int b    = base >> 11;             // / 2048
    const int tid  = threadIdx.x;
    const int lane = tid & 31, w = tid >> 5;

    const unsigned int mb0 = (unsigned int)__cvta_generic_to_shared(&mbar[0]);
    const unsigned int sx0 = (unsigned int)__cvta_generic_to_shared(&sx[0][0][0]);
    const char* gsrc = (const char*)(x + (size_t)base * NH);

    if (tid == 0) {
#pragma unroll
        for (int i = 0; i < PIPE; i++) mbar_init1(mb0 + i * 8);
        asm volatile("fence.proxy.async.shared::cta;" ::: "memory");
    }
    __syncthreads();

    // prologue: issue batches 0 and 1 (one bulk copy each)
    if (tid == 0) {
#pragma unroll
        for (int it = 0; it < 2; it++) {
            mbar_expect_tx(mb0 + it * 8, GBYTES);
            tma_bulk_1d(sx0 + it * GBYTES, gsrc + (size_t)it * GBYTES,
                        GBYTES, mb0 + it * 8);
        }
    }

    // hot per-(b,h) constants in registers
    const float4 C0 = ((const float4*)g_coeff[b][0])[tid];
    const float4 C1 = ((const float4*)g_coeff[b][1])[tid];
    const float4 S1 = ((const float4*)g_coeff[b][2])[tid];
    const float4 C2 = ((const float4*)g_coeff[b][3])[tid];
    const float4 S2 = ((const float4*)g_coeff[b][4])[tid];
    const float4 C3 = ((const float4*)g_coeff[b][5])[tid];
    const float4 S3 = ((const float4*)g_coeff[b][6])[tid];
    float4 p;   // 1 + beta^2
    {
        const float4 sb = ((const float4*)sqrt_beta)[tid];
        p.x = 1.0f + sb.x * sb.x; p.y = 1.0f + sb.y * sb.y;
        p.z = 1.0f + sb.z * sb.z; p.w = 1.0f + sb.w * sb.w;
    }

    float4* __restrict__ orow = (float4*)(out + (size_t)base * NH) + tid;

#pragma unroll
    for (int it = 0; it < NBATCH; it++) {
        if (tid == 0 && it + 2 < NBATCH) {
            const int nb = it + 2;
            mbar_expect_tx(mb0 + (nb % PIPE) * 8, GBYTES);
            tma_bulk_1d(sx0 + (nb % PIPE) * GBYTES, gsrc + (size_t)nb * GBYTES,
                        GBYTES, mb0 + (nb % PIPE) * 8);
        }

        mbar_wait(mb0 + (it % PIPE) * 8, (it / PIPE) & 1);

        const int buf = it % PIPE;
        const int rb  = it & 1;
        const int r0  = it * BATCH;
        float4 val[BATCH];

#pragma unroll
        for (int i = 0; i < BATCH; i++)
            val[i] = sx[buf][i][tid];

        // recombine: val = C0 + sum Ck*ck + Sk*sk + p*x
#pragma unroll
        for (int i = 0; i < BATCH; i++) {
            const int s = (base + r0 + i) & (NS - 1);
            const float4 t0 = *(const float4*)&g_tw[s][0];
            const float4 t1 = *(const float4*)&g_tw[s][4];
            const float c1 = t0.x, s1 = t0.y, c2 = t0.z, s2 = t0.w;
            const float c3 = t1.x, s3 = t1.y;
            const float4 xc = val[i];
            val[i].x = fmaf(p.x, xc.x, C0.x + C1.x*c1 + S1.x*s1 + C2.x*c2 + S2.x*s2 + C3.x*c3 + S3.x*s3);
            val[i].y = fmaf(p.y, xc.y, C0.y + C1.y*c1 + S1.y*s1 + C2.y*c2 + S2.y*s2 + C3.y*c3 + S3.y*s3);
            val[i].z = fmaf(p.z, xc.z, C0.z + C1.z*c1 + S1.z*s1 + C2.z*c2 + S2.z*s2 + C3.z*c3 + S3.z*s3);
            val[i].w = fmaf(p.w, xc.w, C0.w + C1.w*c1 + S1.w*s1 + C2.w*c2 + S2.w*s2 + C3.w*c3 + S3.w*s3);
        }

        // intra-warp reduce per row (shuffle tree)
#pragma unroll
        for (int i = 0; i < BATCH; i++) {
            float lsum = val[i].x + val[i].y + val[i].z + val[i].w;
            float lsq  = val[i].x*val[i].x + val[i].y*val[i].y
                       + val[i].z*val[i].z + val[i].w*val[i].w;
#pragma unroll
            for (int o = 16; o > 0; o >>= 1) {
                lsum += __shfl_down_sync(0xffffffffu, lsum, o);
                lsq  += __shfl_down_sync(0xffffffffu, lsq,  o);
            }
            if (lane == 0) sred[rb][i][w] = make_float2(lsum, lsq);
        }
        __syncthreads();   // one barrier per BATCH rows

        // cross-warp butterfly for all 4 rows at once: lane = row*8 + srcwarp
        const int rr = lane >> 3, ws = lane & 7;
        float a = sred[rb][rr][ws].x;
        float q = sred[rb][rr][ws].y;
#pragma unroll
        for (int o = 4; o > 0; o >>= 1) {
            a += __shfl_down_sync(0xffffffffu, a, o);
            q += __shfl_down_sync(0xffffffffu, q, o);
        }
        // gamma/beta: epilogue-scoped loads (L1-hit after first batch)
        const float4 gv = ldg_f4_nohoist((const float4*)gamma + tid);
        const float4 bv = ldg_f4_nohoist((const float4*)beta  + tid);
#pragma unroll
        for (int i = 0; i < BATCH; i++) {
            const float aa = __shfl_sync(0xffffffffu, a, 8 * i);
            const float qq = __shfl_sync(0xffffffffu, q, 8 * i);
            const float mean = aa * (1.0f / (float)NH);
            const float var  = qq * (1.0f / (float)NH) - mean * mean;
            const float rstd = rsqrtf(var + LN_EPS);
            float4 o4;
            o4.x = fmaf((val[i].x - mean) * rstd, gv.x, bv.x);
            o4.y = fmaf((val[i].y - mean) * rstd, gv.y, bv.y);
            o4.z = fmaf((val[i].z - mean) * rstd, gv.z, bv.z);
            o4.w = fmaf((val[i].w - mean) * rstd, gv.w, bv.w);
            __stcs(&orow[(size_t)(r0 + i) * NH4], o4);
        }
    }
}

// ---------------------------------------------------------------------------
// launch: THREE kernels (twiddle folded into kernel A).
// ---------------------------------------------------------------------------
extern "C" void kernel_launch(void* const* d_in, const int* in_sizes, int n_in,
                              void* d_out, int out_size) {
    const float* x         = (const float*)d_in[0];
    const float* sqrt_beta = (const float*)d_in[1];
    const float* ln_gamma  = (const float*)d_in[2];
    const float* ln_beta   = (const float*)d_in[3];
    float* out = (float*)d_out;

    coeff_partial_kernel<<<NB * NPART, 256>>>(x);

    const int n4 = NB * NCOEF * NH4;
    coeff_reduce_kernel<<<(n4 + 255) / 256, 256>>>(sqrt_beta);

    fuse_ln_kernel<<<NB * NS / ROWS, 256>>>(x, sqrt_beta, ln_gamma, ln_beta, out);
}

// round 17
// speedup vs baseline: 1.0183x; 1.0183x over previous
#include <cuda_runtime.h>
#include <cstdint>
#include <math.h>

#define NB 16
#define NS 2048
#define NH 1024
#define NH4 (NH / 4)
#define NCOEF 7          // C0, C1, S1, C2, S2, C3, S3
#define NPART 37         // 16*37 = 592 = 148*4 CTAs (balanced wave)
#define MAXSEG 56
#define CHUNK 4          // rows per TMA chunk in partial
#define MAXCHK 14        // ceil(56/4)
#define PPIPE 3          // partial smem buffers
#define ROWS 16          // rows per block in fuse_ln
#define BATCH 4          // rows per TMA batch / barrier
#define NBATCH (ROWS / BATCH)  // 4
#define PIPE 3           // fuse smem buffers (2 batches in flight)
#define GBYTES (BATCH * NH * 4)   // 16384 bytes per batch
#define LN_EPS 1e-12f

// twiddles: per s, {cos1,sin1,cos2,sin2,cos3,sin3,0,0}
__device__ __align__(16) float g_tw[NS][8];
__device__ float g_partial[NB][NPART][NCOEF][NH];
__device__ float g_coeff[NB][NCOEF][NH];

__device__ __forceinline__ float4 f4zero() { return make_float4(0.f, 0.f, 0.f, 0.f); }

// ---- TMA bulk 1D (global->shared::cta) + mbarrier helpers -----------------
__device__ __forceinline__ void mbar_init1(unsigned int mbar) {
    asm volatile("mbarrier.init.shared.b64 [%0], 1;" :: "r"(mbar) : "memory");
}
__device__ __forceinline__ void mbar_expect_tx(unsigned int mbar, unsigned int bytes) {
    asm volatile("mbarrier.arrive.expect_tx.shared.b64 _, [%0], %1;"
                 :: "r"(mbar), "r"(bytes) : "memory");
}
__device__ __forceinline__ void tma_bulk_1d(unsigned int sdst, const void* gsrc,
                                            unsigned int bytes, unsigned int mbar) {
    asm volatile("cp.async.bulk.shared::cta.global.mbarrier::complete_tx::bytes "
                 "[%0], [%1], %2, [%3];"
                 :: "r"(sdst), "l"(gsrc), "r"(bytes), "r"(mbar) : "memory");
}
__device__ __forceinline__ void mbar_wait(unsigned int mbar, unsigned int parity) {
    unsigned int done;
    asm volatile(
        "{\n\t.reg .pred p;\n\t"
        "mbarrier.try_wait.parity.acquire.cta.shared::cta.b64 p, [%1], %2;\n\t"
        "selp.b32 %0, 1, 0, p;\n\t}"
        : "=r"(done) : "r"(mbar), "r"(parity) : "memory");
    if (!done) {
        asm volatile(
            "{\n\t.reg .pred P1;\n\t"
            "WAIT_LOOP_%=:\n\t"
            "mbarrier.try_wait.parity.acquire.cta.shared::cta.b64 P1, [%0], %1, 0x989680;\n\t"
            "@P1 bra.uni WAIT_DONE_%=;\n\t"
            "bra.uni WAIT_LOOP_%=;\n\t"
            "WAIT_DONE_%=:\n\t}"
            :: "r"(mbar), "r"(parity) : "memory");
    }
}

// ---------------------------------------------------------------------------
// Kernel A: partial DFT sums with TMA-bulk smem pipeline.
// 592 CTAs = 148*4 balanced wave; each CTA streams 55/56 rows as 14 chunks.
// b==0 CTAs also publish the twiddle table.
// ---------------------------------------------------------------------------
__global__ void __launch_bounds__(256) coeff_partial_kernel(const float* __restrict__ x) {
    __shared__ float4 sxx[PPIPE][CHUNK][NH4];       // 48 KB
    __shared__ float4 tw4[MAXSEG][2];
    __shared__ __align__(8) unsigned long long mbar[PPIPE];

    const int cta = blockIdx.x;
    const int b   = cta / NPART;
    const int j   = cta % NPART;
    const int s_start = (j * NS) / NPART;
    const int s_end   = ((j + 1) * NS) / NPART;
    const int len     = s_end - s_start;          // 55 or 56
    const int nchk    = (len + CHUNK - 1) / CHUNK; // 14
    const int tid     = threadIdx.x;

    const unsigned int mb0 = (unsigned int)__cvta_generic_to_shared(&mbar[0]);
    const unsigned int sx0 = (unsigned int)__cvta_generic_to_shared(&sxx[0][0][0]);
    const char* gsrc = (const char*)(x + ((size_t)b * NS + s_start) * NH);

    if (tid < len) {
        const int s = s_start + tid;
        float cv1, sv1, cv2, sv2, cv3, sv3;
        sincospif((float)s       * (1.0f / 1024.0f), &sv1, &cv1);
        sincospif((float)(2 * s) * (1.0f / 1024.0f), &sv2, &cv2);
        sincospif((float)(3 * s) * (1.0f / 1024.0f), &sv3, &cv3);
        tw4[tid][0] = make_float4(cv1, sv1, cv2, sv2);
        tw4[tid][1] = make_float4(cv3, sv3, 0.f, 0.f);
        if (b == 0) {   // publish twiddle table for fuse_ln
            *(float4*)&g_tw[s][0] = tw4[tid][0];
            *(float4*)&g_tw[s][4] = tw4[tid][1];
        }
    }
    if (tid == 0) {
#pragma unroll
        for (int i = 0; i < PPIPE; i++) mbar_init1(mb0 + i * 8);
        asm volatile("fence.proxy.async.shared::cta;" ::: "memory");
    }
    __syncthreads();

    // prologue: issue chunks 0 and 1
    if (tid == 0) {
#pragma unroll
        for (int c = 0; c < 2; c++) {
            const int rows = min(CHUNK, len - c * CHUNK);
            const unsigned int bytes = (unsigned int)rows * NH * 4;
            mbar_expect_tx(mb0 + c * 8, bytes);
            tma_bulk_1d(sx0 + c * (CHUNK * NH * 4),
                        gsrc + (size_t)c * (CHUNK * NH * 4), bytes, mb0 + c * 8);
        }
    }

    float4 a0 = f4zero(), a1 = f4zero(), b1 = f4zero(),
           a2 = f4zero(), b2 = f4zero(), a3 = f4zero(), b3 = f4zero();

    for (int c = 0; c < MAXCHK; c++) {
        if (c >= nchk) break;
        // buffer (c+2)%3 was consumed in iteration c-1; ensure ALL threads
        // finished it before tid 0 overwrites via TMA
        __syncthreads();
        if (tid == 0 && c + 2 < nchk) {
            const int nc = c + 2;
            const int rows = min(CHUNK, len - nc * CHUNK);
            const unsigned int bytes = (unsigned int)rows * NH * 4;
            mbar_expect_tx(mb0 + (nc % PPIPE) * 8, bytes);
            tma_bulk_1d(sx0 + (nc % PPIPE) * (CHUNK * NH * 4),
                        gsrc + (size_t)nc * (CHUNK * NH * 4), bytes,
                        mb0 + (nc % PPIPE) * 8);
        }
        mbar_wait(mb0 + (c % PPIPE) * 8, (c / PPIPE) & 1);

        const int buf  = c % PPIPE;
        const int r0   = c * CHUNK;
        const int rows = min(CHUNK, len - r0);

#pragma unroll
        for (int i = 0; i < CHUNK; i++) {
            if (i >= rows) break;
            const float4 v  = sxx[buf][i][tid];
            const float4 t0 = tw4[r0 + i][0];
            const float4 t1 = tw4[r0 + i][1];
            const float c1 = t0.x, s1 = t0.y, c2 = t0.z, s2 = t0.w;
            const float c3 = t1.x, s3 = t1.y;
            a0.x += v.x; a0.y += v.y; a0.z += v.z; a0.w += v.w;
            a1.x = fmaf(v.x, c1, a1.x); a1.y = fmaf(v.y, c1, a1.y);
            a1.z = fmaf(v.z, c1, a1.z); a1.w = fmaf(v.w, c1, a1.w);
            b1.x = fmaf(v.x, s1, b1.x); b1.y = fmaf(v.y, s1, b1.y);
            b1.z = fmaf(v.z, s1, b1.z); b1.w = fmaf(v.w, s1, b1.w);
            a2.x = fmaf(v.x, c2, a2.x); a2.y = fmaf(v.y, c2, a2.y);
            a2.z = fmaf(v.z, c2, a2.z); a2.w = fmaf(v.w, c2, a2.w);
            b2.x = fmaf(v.x, s2, b2.x); b2.y = fmaf(v.y, s2, b2.y);
            b2.z = fmaf(v.z, s2, b2.z); b2.w = fmaf(v.w, s2, b2.w);
            a3.x = fmaf(v.x, c3, a3.x); a3.y = fmaf(v.y, c3, a3.y);
            a3.z = fmaf(v.z, c3, a3.z); a3.w = fmaf(v.w, c3, a3.w);
            b3.x = fmaf(v.x, s3, b3.x); b3.y = fmaf(v.y, s3, b3.y);
            b3.z = fmaf(v.z, s3, b3.z); b3.w = fmaf(v.w, s3, b3.w);
        }
    }

    ((float4*)g_partial[b][j][0])[tid] = a0;
    ((float4*)g_partial[b][j][1])[tid] = a1;
    ((float4*)g_partial[b][j][2])[tid] = b1;
    ((float4*)g_partial[b][j][3])[tid] = a2;
    ((float4*)g_partial[b][j][4])[tid] = b2;
    ((float4*)g_partial[b][j][5])[tid] = a3;
    ((float4*)g_partial[b][j][6])[tid] = b3;
}

// ---------------------------------------------------------------------------
// Kernel B: reduce NPART partials (deterministic) and pre-scale.
// ---------------------------------------------------------------------------
__global__ void coeff_reduce_kernel(const float* __restrict__ sqrt_beta) {
    const int i = blockIdx.x * blockDim.x + threadIdx.x;
    const int INNER4 = NCOEF * NH4;
    const int N4 = NB * INNER4;
    if (i >= N4) return;

    const int b  = i / INNER4;
    const int r  = i % INNER4;
    const int k  = r / NH4;
    const int h4 = r % NH4;

    const float4* p4 = (const float4*)&g_partial[b][0][0][0];
    float4 s = f4zero();
#pragma unroll 8
    for (int j = 0; j < NPART; j++) {
        float4 v = p4[(size_t)j * INNER4 + r];
        s.x += v.x; s.y += v.y; s.z += v.z; s.w += v.w;
    }

    const float4 sb = ((const float4*)sqrt_beta)[h4];
    const float base = (k == 0 ? 1.0f : 2.0f) / (float)NS;
    s.x *= (1.0f - sb.x * sb.x) * base;
    s.y *= (1.0f - sb.y * sb.y) * base;
    s.z *= (1.0f - sb.z * sb.z) * base;
    s.w *= (1.0f - sb.w * sb.w) * base;

    ((float4*)&g_coeff[b][k][0])[h4] = s;
}

// ---------------------------------------------------------------------------
// Kernel C: fused recombine + LayerNorm (R15-exact: gamma/beta in smem).
// ---------------------------------------------------------------------------
__global__ void __launch_bounds__(256, 3) fuse_ln_kernel(
    const float* __restrict__ x,
    const float* __restrict__ sqrt_beta,
    const float* __restrict__ gamma,
    const float* __restrict__ beta,
    float* __restrict__ out)
{
    __shared__ float4 sx[PIPE][BATCH][NH4];
    __shared__ float2 sred[2][BATCH][8];
    __shared__ float4 sgb[2][NH4];              // [0]=gamma, [1]=beta
    __shared__ __align__(8) unsigned long long mbar[PIPE];

    const int base = blockIdx.x * ROWS;      // first row (b*NS + s)
    const int b    = base >> 11;             // / 2048
    const int tid  = threadIdx.x;
    const int lane = tid & 31, w = tid >> 5;

    const unsigned int mb0 = (unsigned int)__cvta_generic_to_shared(&mbar[0]);
    const unsigned int sx0 = (unsigned int)__cvta_generic_to_shared(&sx[0][0][0]);
    const char* gsrc = (const char*)(x + (size_t)base * NH);

    if (tid == 0) {
#pragma unroll
        for (int i = 0; i < PIPE; i++) mbar_init1(mb0 + i * 8);
        asm volatile("fence.proxy.async.shared::cta;" ::: "memory");
    }
    // stage gamma/beta into smem (cold constants; frees registers)
    sgb[0][tid] = ((const float4*)gamma)[tid];
    sgb[1][tid] = ((const float4*)beta)[tid];
    __syncthreads();

    // prologue: issue batches 0 and 1 (one bulk copy each)
    if (tid == 0) {
#pragma unroll
        for (int it = 0; it < 2; it++) {
            mbar_expect_tx(mb0 + it * 8, GBYTES);
            tma_bulk_1d(sx0 + it * GBYTES, gsrc + (size_t)it * GBYTES,
                        GBYTES, mb0 + it * 8);
        }
    }

    // hot per-(b,h) constants in registers
    const float4 C0 = ((const float4*)g_coeff[b][0])[tid];
    const float4 C1 = ((const float4*)g_coeff[b][1])[tid];
    const float4 S1 = ((const float4*)g_coeff[b][2])[tid];
    const float4 C2 = ((const float4*)g_coeff[b][3])[tid];
    const float4 S2 = ((const float4*)g_coeff[b][4])[tid];
    const float4 C3 = ((const float4*)g_coeff[b][5])[tid];
    const float4 S3 = ((const float4*)g_coeff[b][6])[tid];
    float4 p;   // 1 + beta^2
    {
        const float4 sb = ((const float4*)sqrt_beta)[tid];
        p.x = 1.0f + sb.x * sb.x; p.y = 1.0f + sb.y * sb.y;
        p.z = 1.0f + sb.z * sb.z; p.w = 1.0f + sb.w * sb.w;
    }

    float4* __restrict__ orow = (float4*)(out + (size_t)base * NH) + tid;

#pragma unroll
    for (int it = 0; it < NBATCH; it++) {
        if (tid == 0 && it + 2 < NBATCH) {
            const int nb = it + 2;
            mbar_expect_tx(mb0 + (nb % PIPE) * 8, GBYTES);
            tma_bulk_1d(sx0 + (nb % PIPE) * GBYTES, gsrc + (size_t)nb * GBYTES,
                        GBYTES, mb0 + (nb % PIPE) * 8);
        }

        mbar_wait(mb0 + (it % PIPE) * 8, (it / PIPE) & 1);

        const int buf = it % PIPE;
        const int rb  = it & 1;
        const int r0  = it * BATCH;
        float4 val[BATCH];

#pragma unroll
        for (int i = 0; i < BATCH; i++)
            val[i] = sx[buf][i][tid];

        // recombine: val = C0 + sum Ck*ck + Sk*sk + p*x
#pragma unroll
        for (int i = 0; i < BATCH; i++) {
            const int s = (base + r0 + i) & (NS - 1);
            const float4 t0 = *(const float4*)&g_tw[s][0];
            const float4 t1 = *(const float4*)&g_tw[s][4];
            const float c1 = t0.x, s1 = t0.y, c2 = t0.z, s2 = t0.w;
            const float c3 = t1.x, s3 = t1.y;
            const float4 xc = val[i];
            val[i].x = fmaf(p.x, xc.x, C0.x + C1.x*c1 + S1.x*s1 + C2.x*c2 + S2.x*s2 + C3.x*c3 + S3.x*s3);
            val[i].y = fmaf(p.y, xc.y, C0.y + C1.y*c1 + S1.y*s1 + C2.y*c2 + S2.y*s2 + C3.y*c3 + S3.y*s3);
            val[i].z = fmaf(p.z, xc.z, C0.z + C1.z*c1 + S1.z*s1 + C2.z*c2 + S2.z*s2 + C3.z*c3 + S3.z*s3);
            val[i].w = fmaf(p.w, xc.w, C0.w + C1.w*c1 + S1.w*s1 + C2.w*c2 + S2.w*s2 + C3.w*c3 + S3.w*s3);
        }

        // intra-warp reduce per row (shuffle tree)
#pragma unroll
        for (int i = 0; i < BATCH; i++) {
            float lsum = val[i].x + val[i].y + val[i].z + val[i].w;
            float lsq  = val[i].x*val[i].x + val[i].y*val[i].y
                       + val[i].z*val[i].z + val[i].w*val[i].w;
#pragma unroll
            for (int o = 16; o > 0; o >>= 1) {
                lsum += __shfl_down_sync(0xffffffffu, lsum, o);
                lsq  += __shfl_down_sync(0xffffffffu, lsq,  o);
            }
            if (lane == 0) sred[rb][i][w] = make_float2(lsum, lsq);
        }
        __syncthreads();   // one barrier per BATCH rows

        // cross-warp butterfly for all 4 rows at once: lane = row*8 + srcwarp
        const int rr = lane >> 3, ws = lane & 7;
        float a = sred[rb][rr][ws].x;
        float q = sred[rb][rr][ws].y;
#pragma unroll
        for (int o = 4; o > 0; o >>= 1) {
            a += __shfl_down_sync(0xffffffffu, a, o);
            q += __shfl_down_sync(0xffffffffu, q, o);
        }
        const float4 gv = sgb[0][tid];
        const float4 bv = sgb[1][tid];
#pragma unroll
        for (int i = 0; i < BATCH; i++) {
            const float aa = __shfl_sync(0xffffffffu, a, 8 * i);
            const float qq = __shfl_sync(0xffffffffu, q, 8 * i);
            const float mean = aa * (1.0f / (float)NH);
            const float var  = qq * (1.0f / (float)NH) - mean * mean;
            const float rstd = rsqrtf(var + LN_EPS);
            float4 o4;
            o4.x = fmaf((val[i].x - mean) * rstd, gv.x, bv.x);
            o4.y = fmaf((val[i].y - mean) * rstd, gv.y, bv.y);
            o4.z = fmaf((val[i].z - mean) * rstd, gv.z, bv.z);
            o4.w = fmaf((val[i].w - mean) * rstd, gv.w, bv.w);
            __stcs(&orow[(size_t)(r0 + i) * NH4], o4);
        }
    }
}

// ---------------------------------------------------------------------------
// launch: THREE kernels.
// ---------------------------------------------------------------------------
extern "C" void kernel_launch(void* const* d_in, const int* in_sizes, int n_in,
                              void* d_out, int out_size) {
    const float* x         = (const float*)d_in[0];
    const float* sqrt_beta = (const float*)d_in[1];
    const float* ln_gamma  = (const float*)d_in[2];
    const float* ln_beta   = (const float*)d_in[3];
    float* out = (float*)d_out;

    coeff_partial_kernel<<<NB * NPART, 256>>>(x);

    const int n4 = NB * NCOEF * NH4;
    coeff_reduce_kernel<<<(n4 + 255) / 256, 256>>>(sqrt_beta);

    fuse_ln_kernel<<<NB * NS / ROWS, 256>>>(x, sqrt_beta, ln_gamma, ln_beta, out);
}